// round 1
// baseline (speedup 1.0000x reference)
#include <cuda_runtime.h>

#define BATCH 32
#define TDIM  2048
#define CDIM  384
#define HDIM  64
#define BT    (BATCH * TDIM)

// Scratch for projected q/k/v: [B*T, H] fp32 each (16 MB apiece).
__device__ float g_q[BT * HDIM];
__device__ float g_k[BT * HDIM];
__device__ float g_v[BT * HDIM];

// ---------------------------------------------------------------------------
// Projection: out[r, h] = sum_c x[r, c] * W[c, h]
// grid = (BT/64, 3), block = 256 (16x16), each thread owns a 4x4 microtile
// (rows ty*4+i, cols tx+16*j). fp32, shared-tiled over C in chunks of 64.
// ---------------------------------------------------------------------------
__global__ __launch_bounds__(256, 4) void proj_kernel(
    const float* __restrict__ x,
    const float* __restrict__ Wk,
    const float* __restrict__ Wq,
    const float* __restrict__ Wv)
{
    __shared__ float Xs[64 * 65];
    __shared__ float Ws[64 * 65];

    const int mtx = blockIdx.y;
    const float* W = (mtx == 0) ? Wk : (mtx == 1) ? Wq : Wv;
    float* outp    = (mtx == 0) ? g_k : (mtx == 1) ? g_q : g_v;

    const int row0 = blockIdx.x * 64;
    const int t  = threadIdx.x;
    const int tx = t & 15;
    const int ty = t >> 4;

    float acc[4][4] = {};

    for (int cc = 0; cc < CDIM; cc += 64) {
        #pragma unroll
        for (int i = 0; i < 16; i++) {
            int idx = t + i * 256;           // 0..4095
            int r = idx >> 6, k = idx & 63;
            Xs[r * 65 + k] = x[(row0 + r) * CDIM + cc + k];
            Ws[r * 65 + k] = W[(cc + r) * HDIM + k];
        }
        __syncthreads();

        #pragma unroll 8
        for (int k = 0; k < 64; k++) {
            float a[4], b[4];
            #pragma unroll
            for (int i = 0; i < 4; i++) a[i] = Xs[(ty * 4 + i) * 65 + k];
            #pragma unroll
            for (int j = 0; j < 4; j++) b[j] = Ws[k * 65 + tx + 16 * j];
            #pragma unroll
            for (int i = 0; i < 4; i++)
                #pragma unroll
                for (int j = 0; j < 4; j++)
                    acc[i][j] = fmaf(a[i], b[j], acc[i][j]);
        }
        __syncthreads();
    }

    #pragma unroll
    for (int i = 0; i < 4; i++)
        #pragma unroll
        for (int j = 0; j < 4; j++)
            outp[(row0 + ty * 4 + i) * HDIM + tx + 16 * j] = acc[i][j];
}

// ---------------------------------------------------------------------------
// Flash attention (fp32, online softmax).
// grid = (T/64 query tiles, B), block = 256 (16x16), 4x4 microtiles.
// Smem (exactly 48 KB static):
//   Qt   [h][r]  transposed, XOR-swizzled, pre-scaled by H^-0.5
//   KtPs [h][c]  transposed K, XOR-swizzled; aliased as P [r][c] (swizzled)
//   Vs   [c][h]  natural layout
// XOR swizzle: element (row-in-smem R, col X) stored at column X ^ (R & 31).
// Makes transposed writes AND strided column reads bank-conflict-free.
// ---------------------------------------------------------------------------
__global__ __launch_bounds__(256) void attn_kernel(float* __restrict__ out)
{
    __shared__ float Qt[64 * 64];
    __shared__ float KtPs[64 * 64];
    __shared__ float Vs[64 * 64];

    const int qt = blockIdx.x;
    const int b  = blockIdx.y;
    const int t  = threadIdx.x;
    const int tx = t & 15;
    const int ty = t >> 4;

    const float* qbase = g_q + (b * TDIM + qt * 64) * HDIM;

    // Load Q tile transposed+swizzled, pre-scaled by 1/sqrt(H) = 0.125
    #pragma unroll
    for (int i = 0; i < 16; i++) {
        int idx = t + i * 256;
        int r = idx >> 6, h = idx & 63;
        Qt[h * 64 + (r ^ (h & 31))] = qbase[r * HDIM + h] * 0.125f;
    }

    float o[4][4] = {};
    float m[4], l[4];
    #pragma unroll
    for (int i = 0; i < 4; i++) { m[i] = -1e30f; l[i] = 0.0f; }

    __syncthreads();

    for (int kt = 0; kt <= qt; kt++) {
        const float* kbase = g_k + (b * TDIM + kt * 64) * HDIM;
        const float* vbase = g_v + (b * TDIM + kt * 64) * HDIM;

        // Load K transposed+swizzled, V natural. (Prev iter's P/V reads are
        // fenced by the syncthreads at the bottom of the loop.)
        #pragma unroll
        for (int i = 0; i < 16; i++) {
            int idx = t + i * 256;
            int c = idx >> 6, h = idx & 63;
            KtPs[h * 64 + (c ^ (h & 31))] = kbase[idx];
            Vs[idx] = vbase[idx];
        }
        __syncthreads();

        // S = Q K^T (scale already folded into Q)
        float s[4][4] = {};
        #pragma unroll 4
        for (int h = 0; h < 64; h++) {
            const int hs = h & 31;
            float a[4], bb[4];
            #pragma unroll
            for (int i = 0; i < 4; i++) a[i]  = Qt[h * 64 + ((ty * 4 + i) ^ hs)];
            #pragma unroll
            for (int j = 0; j < 4; j++) bb[j] = KtPs[h * 64 + ((tx + 16 * j) ^ hs)];
            #pragma unroll
            for (int i = 0; i < 4; i++)
                #pragma unroll
                for (int j = 0; j < 4; j++)
                    s[i][j] = fmaf(a[i], bb[j], s[i][j]);
        }

        // Causal mask (only the diagonal tile needs it)
        if (kt == qt) {
            #pragma unroll
            for (int i = 0; i < 4; i++)
                #pragma unroll
                for (int j = 0; j < 4; j++)
                    if (tx + 16 * j > ty * 4 + i) s[i][j] = -1e30f;
        }

        // Online softmax update
        float corr[4];
        #pragma unroll
        for (int i = 0; i < 4; i++) {
            float mx = fmaxf(fmaxf(s[i][0], s[i][1]), fmaxf(s[i][2], s[i][3]));
            #pragma unroll
            for (int off = 8; off >= 1; off >>= 1)
                mx = fmaxf(mx, __shfl_xor_sync(0xffffffffu, mx, off));
            float mnew = fmaxf(m[i], mx);
            corr[i] = __expf(m[i] - mnew);
            m[i] = mnew;
        }
        #pragma unroll
        for (int i = 0; i < 4; i++) {
            float rs = 0.0f;
            #pragma unroll
            for (int j = 0; j < 4; j++) {
                float p = __expf(s[i][j] - m[i]);
                s[i][j] = p;
                rs += p;
            }
            #pragma unroll
            for (int off = 8; off >= 1; off >>= 1)
                rs += __shfl_xor_sync(0xffffffffu, rs, off);
            l[i] = l[i] * corr[i] + rs;
            #pragma unroll
            for (int j = 0; j < 4; j++) o[i][j] *= corr[i];
        }

        __syncthreads();   // all K reads done before P overwrites the buffer

        // Write P into the K buffer (row-major, swizzled by row)
        #pragma unroll
        for (int i = 0; i < 4; i++) {
            const int r = ty * 4 + i;
            #pragma unroll
            for (int j = 0; j < 4; j++)
                KtPs[r * 64 + ((tx + 16 * j) ^ (r & 31))] = s[i][j];
        }
        __syncthreads();

        // O += P @ V
        #pragma unroll 4
        for (int kc = 0; kc < 64; kc++) {
            float a[4], bb[4];
            #pragma unroll
            for (int i = 0; i < 4; i++) {
                const int r = ty * 4 + i;
                a[i] = KtPs[r * 64 + (kc ^ (r & 31))];
            }
            #pragma unroll
            for (int j = 0; j < 4; j++) bb[j] = Vs[kc * 64 + tx + 16 * j];
            #pragma unroll
            for (int i = 0; i < 4; i++)
                #pragma unroll
                for (int j = 0; j < 4; j++)
                    o[i][j] = fmaf(a[i], bb[j], o[i][j]);
        }
        __syncthreads();   // P/V reads done before next tile's loads
    }

    // Epilogue: normalize and store
    float* ob = out + (b * TDIM + qt * 64) * HDIM;
    #pragma unroll
    for (int i = 0; i < 4; i++) {
        const float inv_l = 1.0f / l[i];
        #pragma unroll
        for (int j = 0; j < 4; j++)
            ob[(ty * 4 + i) * HDIM + tx + 16 * j] = o[i][j] * inv_l;
    }
}

// ---------------------------------------------------------------------------
extern "C" void kernel_launch(void* const* d_in, const int* in_sizes, int n_in,
                              void* d_out, int out_size)
{
    const float* x  = (const float*)d_in[0];
    const float* Wk = (const float*)d_in[1];
    const float* Wq = (const float*)d_in[2];
    const float* Wv = (const float*)d_in[3];
    float* out = (float*)d_out;

    dim3 pgrid(BT / 64, 3);
    proj_kernel<<<pgrid, 256>>>(x, Wk, Wq, Wv);

    dim3 agrid(TDIM / 64, BATCH);
    attn_kernel<<<agrid, 256>>>(out);
}

// round 2
// speedup vs baseline: 2.9308x; 2.9308x over previous
#include <cuda_runtime.h>

#define BATCH 32
#define TDIM  2048
#define CDIM  384
#define HDIM  64
#define BT    (BATCH * TDIM)
#define NQT   (TDIM / 64)          // 32 query tiles of 64 rows

// Scratch for projected q/k/v: [B*T, H] fp32 each.
__device__ float g_q[BT * HDIM];
__device__ float g_k[BT * HDIM];
__device__ float g_v[BT * HDIM];

// Swizzled word index for a transposed 64x64 tile M[outer][inner]:
// float4-group (inner>>2) XORed with (outer&15). Reads of 4 consecutive
// `inner` (aligned group) are a single conflict-free LDS.128.
__device__ __forceinline__ int swz(int outer, int inner) {
    return outer * 64 + ((((inner >> 2) ^ outer) & 15) << 2) + (inner & 3);
}

// ---------------------------------------------------------------------------
// Projection: out[r,h] = sum_c x[r,c] * W[c,h]
// grid = (BT/64, 3), block = 128 (tx 0..15 -> 4 cols, ty 0..7 -> 8 rows).
// Inner loop: 3x LDS.128 + 32 FFMA.
// ---------------------------------------------------------------------------
__global__ __launch_bounds__(128, 6) void proj_kernel(
    const float* __restrict__ x,
    const float* __restrict__ Wk,
    const float* __restrict__ Wq,
    const float* __restrict__ Wv)
{
    __shared__ float Xt[64 * 64];   // transposed+swizzled X chunk [c][r]
    __shared__ float Ws[64 * 64];   // natural W chunk [c][h]

    const int mtx = blockIdx.y;
    const float* W = (mtx == 0) ? Wk : (mtx == 1) ? Wq : Wv;
    float* outp    = (mtx == 0) ? g_k : (mtx == 1) ? g_q : g_v;

    const int row0 = blockIdx.x * 64;
    const int t  = threadIdx.x;
    const int tx = t & 15;
    const int ty = t >> 4;

    float acc[8][4] = {};

    for (int cc = 0; cc < CDIM; cc += 64) {
        #pragma unroll
        for (int i = 0; i < 8; i++) {
            int f  = t + i * 128;          // float4 id 0..1023
            int r  = f >> 4;               // 0..63 (X row / W chunk-row)
            int c0 = (f & 15) * 4;         // inner float4 start
            float4 xv = *(const float4*)&x[(row0 + r) * CDIM + cc + c0];
            Xt[swz(c0 + 0, r)] = xv.x;
            Xt[swz(c0 + 1, r)] = xv.y;
            Xt[swz(c0 + 2, r)] = xv.z;
            Xt[swz(c0 + 3, r)] = xv.w;
            *(float4*)&Ws[r * 64 + c0] = *(const float4*)&W[(cc + r) * HDIM + c0];
        }
        __syncthreads();

        #pragma unroll 16
        for (int k = 0; k < 64; k++) {
            float4 a0 = *(const float4*)&Xt[k * 64 + ((((2 * ty)     ^ k) & 15) << 2)];
            float4 a1 = *(const float4*)&Xt[k * 64 + ((((2 * ty + 1) ^ k) & 15) << 2)];
            float4 b4 = *(const float4*)&Ws[k * 64 + tx * 4];
            float a[8] = {a0.x, a0.y, a0.z, a0.w, a1.x, a1.y, a1.z, a1.w};
            float bb[4] = {b4.x, b4.y, b4.z, b4.w};
            #pragma unroll
            for (int i = 0; i < 8; i++)
                #pragma unroll
                for (int j = 0; j < 4; j++)
                    acc[i][j] = fmaf(a[i], bb[j], acc[i][j]);
        }
        __syncthreads();
    }

    #pragma unroll
    for (int i = 0; i < 8; i++) {
        float4 r4 = make_float4(acc[i][0], acc[i][1], acc[i][2], acc[i][3]);
        *(float4*)&outp[(row0 + ty * 8 + i) * HDIM + tx * 4] = r4;
    }
}

// ---------------------------------------------------------------------------
// Flash attention (fp32, online softmax).
// grid = (NQT/2, B), block = 128. Each block handles q-tiles {z, 31-z}
// -> uniform 33 kt-tiles of work per block, single balanced wave.
// Smem 48 KB: Qt (transposed swizzled), KtP (K transposed / P transposed,
// aliased), Vs (natural). Inner loops: 3x LDS.128 + 32 FFMA.
// ---------------------------------------------------------------------------
__global__ __launch_bounds__(128, 4) void attn_kernel(float* __restrict__ out)
{
    __shared__ float Qt[64 * 64];
    __shared__ float KtP[64 * 64];
    __shared__ float Vs[64 * 64];

    const int b  = blockIdx.y;
    const int t  = threadIdx.x;
    const int tx = t & 15;
    const int ty = t >> 4;

    #pragma unroll 1
    for (int pass = 0; pass < 2; pass++) {
        const int qt = (pass == 0) ? (int)blockIdx.x : (NQT - 1 - (int)blockIdx.x);
        const float* qbase = g_q + (b * TDIM + qt * 64) * HDIM;

        // Load Q transposed+swizzled, pre-scaled by H^-0.5 = 0.125.
        // (end-of-previous-pass __syncthreads guarantees Qt is free)
        #pragma unroll
        for (int i = 0; i < 8; i++) {
            int f  = t + i * 128;
            int r  = f >> 4;
            int h0 = (f & 15) * 4;
            float4 qv = *(const float4*)&qbase[r * HDIM + h0];
            Qt[swz(h0 + 0, r)] = qv.x * 0.125f;
            Qt[swz(h0 + 1, r)] = qv.y * 0.125f;
            Qt[swz(h0 + 2, r)] = qv.z * 0.125f;
            Qt[swz(h0 + 3, r)] = qv.w * 0.125f;
        }

        float o[8][4] = {};
        float m[8], l[8];
        #pragma unroll
        for (int i = 0; i < 8; i++) { m[i] = -1e30f; l[i] = 0.0f; }

        for (int kt = 0; kt <= qt; kt++) {
            const float* kbase = g_k + (b * TDIM + kt * 64) * HDIM;
            const float* vbase = g_v + (b * TDIM + kt * 64) * HDIM;

            // Load K transposed+swizzled into KtP, V natural into Vs.
            #pragma unroll
            for (int i = 0; i < 8; i++) {
                int f  = t + i * 128;
                int c  = f >> 4;
                int h0 = (f & 15) * 4;
                float4 kv = *(const float4*)&kbase[c * HDIM + h0];
                KtP[swz(h0 + 0, c)] = kv.x;
                KtP[swz(h0 + 1, c)] = kv.y;
                KtP[swz(h0 + 2, c)] = kv.z;
                KtP[swz(h0 + 3, c)] = kv.w;
                *(float4*)&Vs[c * 64 + h0] = *(const float4*)&vbase[c * HDIM + h0];
            }
            __syncthreads();

            // S = Q K^T  (scale folded into Q)
            float s[8][4] = {};
            #pragma unroll 16
            for (int h = 0; h < 64; h++) {
                float4 a0 = *(const float4*)&Qt[h * 64 + ((((2 * ty)     ^ h) & 15) << 2)];
                float4 a1 = *(const float4*)&Qt[h * 64 + ((((2 * ty + 1) ^ h) & 15) << 2)];
                float4 b4 = *(const float4*)&KtP[h * 64 + (((tx ^ h) & 15) << 2)];
                float a[8] = {a0.x, a0.y, a0.z, a0.w, a1.x, a1.y, a1.z, a1.w};
                float bb[4] = {b4.x, b4.y, b4.z, b4.w};
                #pragma unroll
                for (int i = 0; i < 8; i++)
                    #pragma unroll
                    for (int j = 0; j < 4; j++)
                        s[i][j] = fmaf(a[i], bb[j], s[i][j]);
            }

            // Causal mask on the diagonal tile
            if (kt == qt) {
                #pragma unroll
                for (int i = 0; i < 8; i++)
                    #pragma unroll
                    for (int j = 0; j < 4; j++)
                        if (tx * 4 + j > ty * 8 + i) s[i][j] = -1e30f;
            }

            // Online softmax (row spans the 16 tx lanes of this ty half-warp)
            #pragma unroll
            for (int i = 0; i < 8; i++) {
                float mx = fmaxf(fmaxf(s[i][0], s[i][1]), fmaxf(s[i][2], s[i][3]));
                #pragma unroll
                for (int off = 8; off >= 1; off >>= 1)
                    mx = fmaxf(mx, __shfl_xor_sync(0xffffffffu, mx, off));
                float mnew = fmaxf(m[i], mx);
                float corr = __expf(m[i] - mnew);
                m[i] = mnew;
                float rs = 0.0f;
                #pragma unroll
                for (int j = 0; j < 4; j++) {
                    float p = __expf(s[i][j] - mnew);
                    s[i][j] = p;
                    rs += p;
                }
                #pragma unroll
                for (int off = 8; off >= 1; off >>= 1)
                    rs += __shfl_xor_sync(0xffffffffu, rs, off);
                l[i] = l[i] * corr + rs;
                #pragma unroll
                for (int j = 0; j < 4; j++) o[i][j] *= corr;
            }

            __syncthreads();   // all K reads done before P overwrites KtP

            // Write P transposed (c-major) + swizzled into KtP
            #pragma unroll
            for (int i = 0; i < 8; i++)
                #pragma unroll
                for (int j = 0; j < 4; j++)
                    KtP[swz(tx * 4 + j, ty * 8 + i)] = s[i][j];
            __syncthreads();

            // O += P @ V
            #pragma unroll 16
            for (int c = 0; c < 64; c++) {
                float4 a0 = *(const float4*)&KtP[c * 64 + ((((2 * ty)     ^ c) & 15) << 2)];
                float4 a1 = *(const float4*)&KtP[c * 64 + ((((2 * ty + 1) ^ c) & 15) << 2)];
                float4 b4 = *(const float4*)&Vs[c * 64 + tx * 4];
                float a[8] = {a0.x, a0.y, a0.z, a0.w, a1.x, a1.y, a1.z, a1.w};
                float bb[4] = {b4.x, b4.y, b4.z, b4.w};
                #pragma unroll
                for (int i = 0; i < 8; i++)
                    #pragma unroll
                    for (int j = 0; j < 4; j++)
                        o[i][j] = fmaf(a[i], bb[j], o[i][j]);
            }
            __syncthreads();   // P/V reads done before next tile's loads
        }

        // Epilogue: normalize and store (float4)
        float* ob = out + (b * TDIM + qt * 64) * HDIM;
        #pragma unroll
        for (int i = 0; i < 8; i++) {
            const float inv_l = 1.0f / l[i];
            float4 r4 = make_float4(o[i][0] * inv_l, o[i][1] * inv_l,
                                    o[i][2] * inv_l, o[i][3] * inv_l);
            *(float4*)&ob[(ty * 8 + i) * HDIM + tx * 4] = r4;
        }
    }
}

// ---------------------------------------------------------------------------
extern "C" void kernel_launch(void* const* d_in, const int* in_sizes, int n_in,
                              void* d_out, int out_size)
{
    const float* x  = (const float*)d_in[0];
    const float* Wk = (const float*)d_in[1];
    const float* Wq = (const float*)d_in[2];
    const float* Wv = (const float*)d_in[3];
    float* out = (float*)d_out;

    dim3 pgrid(BT / 64, 3);
    proj_kernel<<<pgrid, 128>>>(x, Wk, Wq, Wv);

    dim3 agrid(NQT / 2, BATCH);
    attn_kernel<<<agrid, 128>>>(out);
}

// round 4
// speedup vs baseline: 9.3137x; 3.1778x over previous
#include <cuda_runtime.h>
#include <cstdint>

#define BATCH 32
#define TDIM  2048
#define CDIM  384
#define HDIM  64
#define BT    (BATCH * TDIM)

// Projected activations, natural [t][h] layout.
__device__ float g_q[BT * HDIM];
__device__ float g_k[BT * HDIM];
__device__ float g_v[BT * HDIM];

__device__ __forceinline__ float tf32r(float x) {
    asm("cvt.rna.tf32.f32 %0, %1;" : "=f"(x) : "f"(x));
    return x;
}
__device__ __forceinline__ uint32_t fu(float x) { return __float_as_uint(x); }

// m16n8k8 tf32 MMA, D = A*B + D.
// A frag (per lane): a0(r=l>>2, k=l&3) a1(r+8, k) a2(r, k+4) a3(r+8, k+4)
// B frag: b0(k=l&3, n=l>>2) b1(k+4, n)
// C frag: c0(r=l>>2, n=2*(l&3)) c1(n+1) c2(r+8, n) c3(r+8, n+1)
__device__ __forceinline__ void mma8(float4& c, const uint32_t a[4],
                                     uint32_t b0, uint32_t b1) {
    asm volatile(
        "mma.sync.aligned.m16n8k8.row.col.f32.tf32.tf32.f32 "
        "{%0,%1,%2,%3}, {%4,%5,%6,%7}, {%8,%9}, {%0,%1,%2,%3};"
        : "+f"(c.x), "+f"(c.y), "+f"(c.z), "+f"(c.w)
        : "r"(a[0]), "r"(a[1]), "r"(a[2]), "r"(a[3]), "r"(b0), "r"(b1));
}

// ---------------------------------------------------------------------------
// Projection: [K|Q|V] = x @ [Wk|Wq|Wv].  Block = 256 thr (8 warps) x 128 rows.
// Per warp: 16 rows x 192 cols = 24 C-tiles. K streamed in 12 chunks of 32.
// Xs pitch 36 -> A-frag LDS conflict-free; Ws pitch 72 -> B-frag conflict-free.
// ---------------------------------------------------------------------------
__global__ __launch_bounds__(256, 1) void proj_kernel(
    const float* __restrict__ x,
    const float* __restrict__ Wk,
    const float* __restrict__ Wq,
    const float* __restrict__ Wv)
{
    __shared__ float Xs[128 * 36];
    __shared__ float Ws[3 * 32 * 72];

    const int t    = threadIdx.x;
    const int warp = t >> 5;
    const int lane = t & 31;
    const int q    = lane & 3;
    const int r4   = lane >> 2;
    const int row0 = blockIdx.x * 128;
    const float* Wm[3] = {Wk, Wq, Wv};

    float4 c[24];
    #pragma unroll
    for (int i = 0; i < 24; i++) c[i] = make_float4(0.f, 0.f, 0.f, 0.f);

    // prefetch chunk 0
    float4 xr[4], wr[6];
    #pragma unroll
    for (int i = 0; i < 4; i++) {
        int f = t + i * 256, r = f >> 3, c4 = f & 7;
        xr[i] = *(const float4*)&x[(row0 + r) * CDIM + c4 * 4];
    }
    #pragma unroll
    for (int j = 0; j < 6; j++) {
        int g = t + (j & 1) * 256, k = g >> 4, h4 = g & 15;
        wr[j] = *(const float4*)&Wm[j >> 1][k * HDIM + h4 * 4];
    }

    for (int cc = 0; cc < 12; cc++) {
        __syncthreads();
        #pragma unroll
        for (int i = 0; i < 4; i++) {
            int f = t + i * 256, r = f >> 3, c4 = f & 7;
            *(float4*)&Xs[r * 36 + c4 * 4] = make_float4(
                tf32r(xr[i].x), tf32r(xr[i].y), tf32r(xr[i].z), tf32r(xr[i].w));
        }
        #pragma unroll
        for (int j = 0; j < 6; j++) {
            int g = t + (j & 1) * 256, k = g >> 4, h4 = g & 15;
            *(float4*)&Ws[(j >> 1) * 2304 + k * 72 + h4 * 4] = make_float4(
                tf32r(wr[j].x), tf32r(wr[j].y), tf32r(wr[j].z), tf32r(wr[j].w));
        }
        __syncthreads();

        if (cc + 1 < 12) {
            const int c0 = (cc + 1) * 32;
            #pragma unroll
            for (int i = 0; i < 4; i++) {
                int f = t + i * 256, r = f >> 3, c4 = f & 7;
                xr[i] = *(const float4*)&x[(row0 + r) * CDIM + c0 + c4 * 4];
            }
            #pragma unroll
            for (int j = 0; j < 6; j++) {
                int g = t + (j & 1) * 256, k = g >> 4, h4 = g & 15;
                wr[j] = *(const float4*)&Wm[j >> 1][(c0 + k) * HDIM + h4 * 4];
            }
        }

        uint32_t a[4][4];
        #pragma unroll
        for (int kc = 0; kc < 4; kc++) {
            const int rb = (warp * 16 + r4) * 36 + 8 * kc + q;
            a[kc][0] = fu(Xs[rb]);
            a[kc][1] = fu(Xs[rb + 8 * 36]);
            a[kc][2] = fu(Xs[rb + 4]);
            a[kc][3] = fu(Xs[rb + 8 * 36 + 4]);
        }
        #pragma unroll
        for (int mat = 0; mat < 3; mat++)
            #pragma unroll
            for (int nc = 0; nc < 8; nc++)
                #pragma unroll
                for (int kc = 0; kc < 4; kc++) {
                    uint32_t b0 = fu(Ws[mat * 2304 + (8 * kc + q)     * 72 + 8 * nc + r4]);
                    uint32_t b1 = fu(Ws[mat * 2304 + (8 * kc + q + 4) * 72 + 8 * nc + r4]);
                    mma8(c[mat * 8 + nc], a[kc], b0, b1);
                }
    }

    const int row = row0 + warp * 16 + r4;
    float* outp[3] = {g_k, g_q, g_v};
    #pragma unroll
    for (int mat = 0; mat < 3; mat++)
        #pragma unroll
        for (int nc = 0; nc < 8; nc++) {
            const int col = 8 * nc + 2 * q;
            float4 v = c[mat * 8 + nc];
            *(float2*)&outp[mat][row * HDIM + col]       = make_float2(v.x, v.y);
            *(float2*)&outp[mat][(row + 8) * HDIM + col] = make_float2(v.z, v.w);
        }
}

// ---------------------------------------------------------------------------
// Flash attention with warp-MMA (tf32). Block = 256 thr, 128 q-rows.
// Per kt tile: S = Q@K^T (Q frags in regs, K B-frags from smem pitch 68),
// thread-local softmax (C rows live in quads), P C->A via register shuffles,
// PV accumulates into O C-frags (V B-frags from smem pitch 72).
// K/V of next tile prefetched into registers during compute.
// ---------------------------------------------------------------------------
__global__ __launch_bounds__(256, 1) void attn_kernel(float* __restrict__ out)
{
    __shared__ float Ks[64 * 68];
    __shared__ float Vs[64 * 72];

    const int t    = threadIdx.x;
    const int b    = blockIdx.y;
    const int warp = t >> 5;
    const int lane = t & 31;
    const int q    = lane & 3;
    const int r4   = lane >> 2;
    const int srcA = (lane & ~3) | (q >> 1);
    const int srcB = srcA + 2;

    #pragma unroll 1
    for (int pass = 0; pass < 2; pass++) {
        const int qt = pass ? (15 - (int)blockIdx.x) : (int)blockIdx.x;
        const int row_lo = qt * 128 + warp * 16 + r4;   // this thread's low row

        // Q fragments (pre-scaled by H^-0.5)
        uint32_t qa[8][4];
        {
            const float* qp = g_q + (b * TDIM + row_lo) * HDIM;
            #pragma unroll
            for (int kc = 0; kc < 8; kc++) {
                qa[kc][0] = fu(tf32r(qp[8 * kc + q] * 0.125f));
                qa[kc][1] = fu(tf32r(qp[8 * HDIM + 8 * kc + q] * 0.125f));
                qa[kc][2] = fu(tf32r(qp[8 * kc + q + 4] * 0.125f));
                qa[kc][3] = fu(tf32r(qp[8 * HDIM + 8 * kc + q + 4] * 0.125f));
            }
        }

        float4 o[8];
        #pragma unroll
        for (int i = 0; i < 8; i++) o[i] = make_float4(0.f, 0.f, 0.f, 0.f);
        float m0 = -1e30f, m1 = -1e30f, l0 = 0.f, l1 = 0.f;

        const int nkt = 2 * qt + 2;

        // prefetch tile 0
        float4 kr[4], vr[4];
        {
            const float4* kb = (const float4*)(g_k + (b * TDIM) * HDIM);
            const float4* vb = (const float4*)(g_v + (b * TDIM) * HDIM);
            #pragma unroll
            for (int i = 0; i < 4; i++) { kr[i] = kb[t + i * 256]; vr[i] = vb[t + i * 256]; }
        }

        for (int kt = 0; kt < nkt; kt++) {
            __syncthreads();
            #pragma unroll
            for (int i = 0; i < 4; i++) {
                int f = t + i * 256, key = f >> 4, h4 = (f & 15) * 4;
                *(float4*)&Ks[key * 68 + h4] = make_float4(
                    tf32r(kr[i].x), tf32r(kr[i].y), tf32r(kr[i].z), tf32r(kr[i].w));
                *(float4*)&Vs[key * 72 + h4] = make_float4(
                    tf32r(vr[i].x), tf32r(vr[i].y), tf32r(vr[i].z), tf32r(vr[i].w));
            }
            __syncthreads();

            if (kt + 1 < nkt) {
                const float4* kb = (const float4*)(g_k + (b * TDIM + (kt + 1) * 64) * HDIM);
                const float4* vb = (const float4*)(g_v + (b * TDIM + (kt + 1) * 64) * HDIM);
                #pragma unroll
                for (int i = 0; i < 4; i++) { kr[i] = kb[t + i * 256]; vr[i] = vb[t + i * 256]; }
            }

            // S = Q @ K^T
            float4 st[8];
            #pragma unroll
            for (int i = 0; i < 8; i++) st[i] = make_float4(0.f, 0.f, 0.f, 0.f);
            #pragma unroll
            for (int nc = 0; nc < 8; nc++) {
                const int rb = (8 * nc + r4) * 68;
                #pragma unroll
                for (int kc = 0; kc < 8; kc++) {
                    uint32_t b0 = fu(Ks[rb + 8 * kc + q]);
                    uint32_t b1 = fu(Ks[rb + 8 * kc + q + 4]);
                    mma8(st[nc], qa[kc], b0, b1);
                }
            }

            // causal mask (only the last two tiles can clip)
            if (kt >= nkt - 2) {
                const int cb = kt * 64 + 2 * q;
                #pragma unroll
                for (int nc = 0; nc < 8; nc++) {
                    const int col = cb + 8 * nc;
                    if (col > row_lo)         st[nc].x = -1e30f;
                    if (col + 1 > row_lo)     st[nc].y = -1e30f;
                    if (col > row_lo + 8)     st[nc].z = -1e30f;
                    if (col + 1 > row_lo + 8) st[nc].w = -1e30f;
                }
            }

            // online softmax (rows r4 and r4+8; row spread across the quad)
            float mx0 = st[0].x, mx1 = st[0].z;
            #pragma unroll
            for (int nc = 0; nc < 8; nc++) {
                mx0 = fmaxf(mx0, fmaxf(st[nc].x, st[nc].y));
                mx1 = fmaxf(mx1, fmaxf(st[nc].z, st[nc].w));
            }
            mx0 = fmaxf(mx0, __shfl_xor_sync(0xffffffffu, mx0, 1));
            mx0 = fmaxf(mx0, __shfl_xor_sync(0xffffffffu, mx0, 2));
            mx1 = fmaxf(mx1, __shfl_xor_sync(0xffffffffu, mx1, 1));
            mx1 = fmaxf(mx1, __shfl_xor_sync(0xffffffffu, mx1, 2));
            const float mn0 = fmaxf(m0, mx0), mn1 = fmaxf(m1, mx1);
            const float corr0 = __expf(m0 - mn0), corr1 = __expf(m1 - mn1);
            m0 = mn0; m1 = mn1;

            float s0 = 0.f, s1 = 0.f;
            #pragma unroll
            for (int nc = 0; nc < 8; nc++) {
                st[nc].x = tf32r(__expf(st[nc].x - mn0));
                st[nc].y = tf32r(__expf(st[nc].y - mn0));
                st[nc].z = tf32r(__expf(st[nc].z - mn1));
                st[nc].w = tf32r(__expf(st[nc].w - mn1));
                s0 += st[nc].x + st[nc].y;
                s1 += st[nc].z + st[nc].w;
            }
            l0 = l0 * corr0 + s0;
            l1 = l1 * corr1 + s1;
            #pragma unroll
            for (int nc = 0; nc < 8; nc++) {
                o[nc].x *= corr0; o[nc].y *= corr0;
                o[nc].z *= corr1; o[nc].w *= corr1;
            }

            // O += P @ V   (P: C-frag -> A-frag via quad shuffles)
            #pragma unroll
            for (int kc = 0; kc < 8; kc++) {
                float u0 = __shfl_sync(0xffffffffu, st[kc].x, srcA);
                float u1 = __shfl_sync(0xffffffffu, st[kc].y, srcA);
                float a0f = (q & 1) ? u1 : u0;
                u0 = __shfl_sync(0xffffffffu, st[kc].z, srcA);
                u1 = __shfl_sync(0xffffffffu, st[kc].w, srcA);
                float a1f = (q & 1) ? u1 : u0;
                u0 = __shfl_sync(0xffffffffu, st[kc].x, srcB);
                u1 = __shfl_sync(0xffffffffu, st[kc].y, srcB);
                float a2f = (q & 1) ? u1 : u0;
                u0 = __shfl_sync(0xffffffffu, st[kc].z, srcB);
                u1 = __shfl_sync(0xffffffffu, st[kc].w, srcB);
                float a3f = (q & 1) ? u1 : u0;
                uint32_t a[4] = {fu(a0f), fu(a1f), fu(a2f), fu(a3f)};

                const int vb0 = (8 * kc + q) * 72 + r4;
                const int vb1 = (8 * kc + q + 4) * 72 + r4;
                #pragma unroll
                for (int nc = 0; nc < 8; nc++) {
                    uint32_t b0 = fu(Vs[vb0 + 8 * nc]);
                    uint32_t b1 = fu(Vs[vb1 + 8 * nc]);
                    mma8(o[nc], a, b0, b1);
                }
            }
        }

        // epilogue
        l0 += __shfl_xor_sync(0xffffffffu, l0, 1);
        l0 += __shfl_xor_sync(0xffffffffu, l0, 2);
        l1 += __shfl_xor_sync(0xffffffffu, l1, 1);
        l1 += __shfl_xor_sync(0xffffffffu, l1, 2);
        const float inv0 = 1.0f / l0, inv1 = 1.0f / l1;

        float* ob = out + (b * TDIM + row_lo) * HDIM;
        #pragma unroll
        for (int nc = 0; nc < 8; nc++) {
            const int col = 8 * nc + 2 * q;
            *(float2*)&ob[col]            = make_float2(o[nc].x * inv0, o[nc].y * inv0);
            *(float2*)&ob[8 * HDIM + col] = make_float2(o[nc].z * inv1, o[nc].w * inv1);
        }
    }
}

// ---------------------------------------------------------------------------
extern "C" void kernel_launch(void* const* d_in, const int* in_sizes, int n_in,
                              void* d_out, int out_size)
{
    const float* x  = (const float*)d_in[0];
    const float* Wk = (const float*)d_in[1];
    const float* Wq = (const float*)d_in[2];
    const float* Wv = (const float*)d_in[3];
    float* out = (float*)d_out;

    proj_kernel<<<BT / 128, 256>>>(x, Wk, Wq, Wv);

    dim3 agrid(8, BATCH);   // qt pairs {z, 15-z} x batches
    attn_kernel<<<agrid, 256>>>(out);
}